// round 8
// baseline (speedup 1.0000x reference)
#include <cuda_runtime.h>
#include <math.h>
#include <limits.h>

// Problem constants: B=4096, DIM=512, C=128, TEMP=0.05
#define MAXB 8192
#define MAXC 128
#define DIM  512
#define CHUNK 32
#define PAD   516     // words per staged row: 516%32==4, float4-aligned, conflict-free
#define THREADS 128
#define SPLIT 2       // blocks per bucket

__device__ int   g_bstart[MAXC + 1];
__device__ int   g_bidx[MAXB];
__device__ float g_sum;
__device__ float g_cnt;
__device__ int   g_done;

// ---------------------------------------------------------------------------
// Kernel 1: build label buckets (CSR) + zero accumulators. Single block.
// ---------------------------------------------------------------------------
__global__ void __launch_bounds__(1024)
build_kernel(const int* __restrict__ labels, int n, int C)
{
    __shared__ int s_cnt[MAXC];
    __shared__ int s_scat[MAXC];
    __shared__ int s_wsum[4];
    __shared__ int s_lab[MAXB];
    int tid = threadIdx.x;

    for (int c = tid; c < MAXC; c += blockDim.x) s_cnt[c] = 0;
    if (tid == 0) { g_sum = 0.0f; g_cnt = 0.0f; g_done = 0; }
    __syncthreads();

    for (int i = tid; i < n; i += blockDim.x) {
        int l = labels[i];
        l = (l < 0) ? 0 : (l >= C ? C - 1 : l);
        s_lab[i] = l;
        atomicAdd(&s_cnt[l], 1);
    }
    __syncthreads();

    int incl_local = 0;
    if (tid < MAXC) {
        int lane = tid & 31, w = tid >> 5;
        int x = s_cnt[tid];
        #pragma unroll
        for (int o = 1; o < 32; o <<= 1) {
            int y = __shfl_up_sync(0xFFFFFFFFu, x, o);
            if (lane >= o) x += y;
        }
        if (lane == 31) s_wsum[w] = x;
        incl_local = x;
    }
    __syncthreads();
    if (tid < MAXC) {
        int w = tid >> 5;
        int add = 0;
        #pragma unroll
        for (int k = 0; k < 4; k++) add += (k < w) ? s_wsum[k] : 0;
        int incl = incl_local + add;
        int excl = incl - s_cnt[tid];
        g_bstart[tid] = excl;
        s_scat[tid]   = excl;
        if (tid == MAXC - 1) g_bstart[MAXC] = incl;
    }
    __syncthreads();

    for (int i = tid; i < n; i += blockDim.x) {
        int l = s_lab[i];
        int p = atomicAdd(&s_scat[l], 1);
        g_bidx[p] = i;
    }
}

// ---------------------------------------------------------------------------
__device__ __forceinline__ float warp_sum(float v)
{
    #pragma unroll
    for (int o = 16; o > 0; o >>= 1)
        v += __shfl_xor_sync(0xFFFFFFFFu, v, o);
    return v;
}

// direct squared distance between global rows a,b (warp-cooperative, matches _pair_dist)
__device__ __forceinline__ float direct_d2(const float* __restrict__ batch,
                                           int a, int b, int lane)
{
    const float4* ra = (const float4*)(batch + (size_t)a * DIM);
    const float4* rb = (const float4*)(batch + (size_t)b * DIM);
    float c0 = 0.f, c1 = 0.f;
    #pragma unroll
    for (int q = 0; q < 4; q++) {
        float4 x = ra[lane + 32 * q];
        float4 y = rb[lane + 32 * q];
        float d;
        d = x.x - y.x; c0 = fmaf(d, d, c0);
        d = x.y - y.y; c1 = fmaf(d, d, c1);
        d = x.z - y.z; c0 = fmaf(d, d, c0);
        d = x.w - y.w; c1 = fmaf(d, d, c1);
    }
    return warp_sum(c0 + c1);
}

extern __shared__ float s_j[];   // CHUNK * PAD floats = 66048 bytes

// ---------------------------------------------------------------------------
// Kernel 2: SPLIT blocks per bucket; lanes own candidates, warps own 4 anchors.
// ---------------------------------------------------------------------------
__global__ void __launch_bounds__(THREADS)
bucket_kernel(const float* __restrict__ batch,
              const int* __restrict__ anchors,
              const int* __restrict__ negatives,
              float* __restrict__ out)
{
    __shared__ int   s_ji[CHUNK];
    __shared__ float s_n[CHUNK];
    __shared__ float s_bsum;
    __shared__ int   s_bcnt;

    int c    = blockIdx.x >> 1;          // bucket
    int h    = blockIdx.x & 1;           // half (interleaved slots)
    int s    = g_bstart[c];
    int e    = g_bstart[c + 1];
    int m    = e - s;
    int tid  = threadIdx.x;
    int w    = tid >> 5;                 // warp 0..3
    int lane = tid & 31;

    if (tid == 0) { s_bsum = 0.f; s_bcnt = 0; }

    if (m > 2) {
        // passes over this block's anchor slots: s+h, s+h+2, ... (stride 2)
        for (int pbase = 0; s + h + 2 * pbase < e; pbase += 16) {
            // this warp's 4 anchors
            int tg[4]; bool av[4]; const float4* apt[4];
            #pragma unroll
            for (int g = 0; g < 4; g++) {
                int sl = s + h + 2 * (pbase + w * 4 + g);
                av[g]  = sl < e;
                tg[g]  = g_bidx[av[g] ? sl : s];
                apt[g] = (const float4*)(batch + (size_t)tg[g] * DIM);
            }
            float best[4]; int bj[4];
            #pragma unroll
            for (int g = 0; g < 4; g++) { best[g] = INFINITY; bj[g] = INT_MAX; }

            for (int cb = s; cb < e; cb += CHUNK) {
                int cm = min(CHUNK, e - cb);
                __syncthreads();           // prior chunk consumers done
                // stage cm candidate rows (coalesced global -> padded smem)
                for (int idx = tid; idx < cm * 128; idx += THREADS) {
                    int r  = idx >> 7;
                    int k4 = idx & 127;
                    int j  = g_bidx[cb + r];
                    float4 v = ((const float4*)(batch + (size_t)j * DIM))[k4];
                    *((float4*)(s_j + r * PAD + k4 * 4)) = v;
                }
                if (tid < CHUNK) s_ji[tid] = g_bidx[cb + min(tid, cm - 1)];
                __syncthreads();
                // candidate norms
                for (int r = w; r < cm; r += 4) {
                    const float4* rp = (const float4*)(s_j + r * PAD);
                    float na = 0.f, nb = 0.f;
                    #pragma unroll
                    for (int q = 0; q < 4; q++) {
                        float4 v = rp[lane + 32 * q];
                        na = fmaf(v.x, v.x, na); nb = fmaf(v.y, v.y, nb);
                        na = fmaf(v.z, v.z, na); nb = fmaf(v.w, v.w, nb);
                    }
                    float nn = warp_sum(na + nb);
                    if (lane == 0) s_n[r] = nn;
                }
                __syncthreads();

                bool  lv  = lane < cm;
                int   j   = s_ji[lane];
                float nrm = s_n[lane];
                const float4* sl4 = (const float4*)(s_j + lane * PAD);

                float d0a = 0.f, d0b = 0.f, d1a = 0.f, d1b = 0.f;
                float d2a = 0.f, d2b = 0.f, d3a = 0.f, d3b = 0.f;
                #pragma unroll 4
                for (int k4 = 0; k4 < 128; k4++) {
                    float4 cv = sl4[k4];                 // lane-private candidate
                    float4 a0 = __ldg(apt[0] + k4);      // broadcast anchors
                    float4 a1 = __ldg(apt[1] + k4);
                    float4 a2 = __ldg(apt[2] + k4);
                    float4 a3 = __ldg(apt[3] + k4);
                    d0a = fmaf(a0.x, cv.x, d0a); d0b = fmaf(a0.y, cv.y, d0b);
                    d0a = fmaf(a0.z, cv.z, d0a); d0b = fmaf(a0.w, cv.w, d0b);
                    d1a = fmaf(a1.x, cv.x, d1a); d1b = fmaf(a1.y, cv.y, d1b);
                    d1a = fmaf(a1.z, cv.z, d1a); d1b = fmaf(a1.w, cv.w, d1b);
                    d2a = fmaf(a2.x, cv.x, d2a); d2b = fmaf(a2.y, cv.y, d2b);
                    d2a = fmaf(a2.z, cv.z, d2a); d2b = fmaf(a2.w, cv.w, d2b);
                    d3a = fmaf(a3.x, cv.x, d3a); d3b = fmaf(a3.y, cv.y, d3b);
                    d3a = fmaf(a3.z, cv.z, d3a); d3b = fmaf(a3.w, cv.w, d3b);
                }
                float dot[4] = { d0a + d0b, d1a + d1b, d2a + d2b, d3a + d3b };
                #pragma unroll
                for (int g = 0; g < 4; g++) {
                    float mg = fmaf(-2.f, dot[g], nrm);  // ||c||^2 - 2<a,c>
                    if (!lv || j == tg[g]) mg = INFINITY;
                    if (mg < best[g] || (mg == best[g] && j < bj[g])) {
                        best[g] = mg; bj[g] = j;
                    }
                }
            } // chunks

            // per-anchor argmin across lanes, then loss terms
            #pragma unroll
            for (int g = 0; g < 4; g++) {
                float b = best[g]; int j = bj[g];
                #pragma unroll
                for (int o = 16; o > 0; o >>= 1) {
                    float ob = __shfl_xor_sync(0xFFFFFFFFu, b, o);
                    int   oj = __shfl_xor_sync(0xFFFFFFFFu, j, o);
                    if (ob < b || (ob == b && oj < j)) { b = ob; j = oj; }
                }
                if (av[g]) {                       // warp-uniform (depends on w,g)
                    int t  = tg[g];
                    int a  = anchors[t];
                    int ng = negatives[t];
                    float dap2 = direct_d2(batch, a, j,  lane);
                    float dan2 = direct_d2(batch, a, ng, lane);
                    if (lane == 0) {
                        float d_ap = sqrtf(fmaxf(dap2, 1e-12f));
                        float d_an = sqrtf(fmaxf(dan2, 1e-12f));
                        float z    = (d_ap - d_an) * 10.0f;  // (s_an-s_ap)/0.05
                        float per  = fmaxf(z, 0.f) + log1pf(expf(-fabsf(z)));
                        atomicAdd(&s_bsum, per);
                        atomicAdd(&s_bcnt, 1);
                    }
                }
            }
        } // passes
    }

    __syncthreads();
    if (tid == 0) {
        if (s_bcnt > 0) {
            atomicAdd(&g_sum, s_bsum);
            atomicAdd(&g_cnt, (float)s_bcnt);
        }
        __threadfence();
        int done = atomicAdd(&g_done, 1);
        if (done == (int)gridDim.x - 1) {
            float sum = atomicAdd(&g_sum, 0.0f);
            float cn  = atomicAdd(&g_cnt, 0.0f);
            out[0] = sum / cn;
        }
    }
}

// ---------------------------------------------------------------------------
extern "C" void kernel_launch(void* const* d_in, const int* in_sizes, int n_in,
                              void* d_out, int out_size)
{
    const float* batch     = (const float*)d_in[0];
    const int*   labels    = (const int*)d_in[1];
    const int*   anchors   = (const int*)d_in[2];
    const int*   negatives = (const int*)d_in[3];
    float*       out       = (float*)d_out;

    int n = in_sizes[1];
    int C = 128;
    int dyn = CHUNK * PAD * (int)sizeof(float);   // 66048 B

    cudaFuncSetAttribute(bucket_kernel,
                         cudaFuncAttributeMaxDynamicSharedMemorySize, dyn);

    build_kernel<<<1, 1024>>>(labels, n, C);
    bucket_kernel<<<C * SPLIT, THREADS, dyn>>>(batch, anchors, negatives, out);
}

// round 9
// speedup vs baseline: 3.5030x; 3.5030x over previous
#include <cuda_runtime.h>
#include <math.h>
#include <limits.h>

// Problem constants: B=4096, DIM=512, C=128, TEMP=0.05
#define MAXB 8192
#define MAXC 128
#define DIM  512

__device__ int   g_lab[MAXB];
__device__ int   g_bstart[MAXC + 1];
__device__ int   g_bidx[MAXB];
__device__ float g_norm[MAXB];
__device__ float g_sum;
__device__ float g_cnt;
__device__ int   g_done;

// ---------------------------------------------------------------------------
// Kernel 1: build label buckets (CSR) + zero accumulators. Single block.
// ---------------------------------------------------------------------------
__global__ void __launch_bounds__(1024)
build_kernel(const int* __restrict__ labels, int n, int C)
{
    __shared__ int s_cnt[MAXC];
    __shared__ int s_scat[MAXC];
    __shared__ int s_wsum[4];
    __shared__ int s_lab[MAXB];
    int tid = threadIdx.x;

    for (int c = tid; c < MAXC; c += blockDim.x) s_cnt[c] = 0;
    if (tid == 0) { g_sum = 0.0f; g_cnt = 0.0f; g_done = 0; }
    __syncthreads();

    for (int i = tid; i < n; i += blockDim.x) {
        int l = labels[i];
        l = (l < 0) ? 0 : (l >= C ? C - 1 : l);
        s_lab[i] = l;
        g_lab[i] = l;
        atomicAdd(&s_cnt[l], 1);
    }
    __syncthreads();

    int incl_local = 0;
    if (tid < MAXC) {
        int lane = tid & 31, w = tid >> 5;
        int x = s_cnt[tid];
        #pragma unroll
        for (int o = 1; o < 32; o <<= 1) {
            int y = __shfl_up_sync(0xFFFFFFFFu, x, o);
            if (lane >= o) x += y;
        }
        if (lane == 31) s_wsum[w] = x;
        incl_local = x;
    }
    __syncthreads();
    if (tid < MAXC) {
        int w = tid >> 5;
        int add = 0;
        #pragma unroll
        for (int k = 0; k < 4; k++) add += (k < w) ? s_wsum[k] : 0;
        int incl = incl_local + add;
        int excl = incl - s_cnt[tid];
        g_bstart[tid] = excl;
        s_scat[tid]   = excl;
        if (tid == MAXC - 1) g_bstart[MAXC] = incl;
    }
    __syncthreads();

    for (int i = tid; i < n; i += blockDim.x) {
        int l = s_lab[i];
        int p = atomicAdd(&s_scat[l], 1);
        g_bidx[p] = i;
    }
}

// ---------------------------------------------------------------------------
__device__ __forceinline__ float warp_sum(float v)
{
    #pragma unroll
    for (int o = 16; o > 0; o >>= 1)
        v += __shfl_xor_sync(0xFFFFFFFFu, v, o);
    return v;
}

// ---------------------------------------------------------------------------
// Kernel 1b: row norms (warp per row). Also warms L2 with the batch.
// ---------------------------------------------------------------------------
__global__ void __launch_bounds__(256)
norm_kernel(const float* __restrict__ batch, int n)
{
    int gw   = (blockIdx.x * blockDim.x + threadIdx.x) >> 5;
    int lane = threadIdx.x & 31;
    if (gw >= n) return;
    const float4* r = (const float4*)(batch + (size_t)gw * DIM);
    float a = 0.f, b = 0.f;
    #pragma unroll
    for (int q = 0; q < 4; q++) {
        float4 v = r[lane + 32 * q];
        a = fmaf(v.x, v.x, a); b = fmaf(v.y, v.y, b);
        a = fmaf(v.z, v.z, a); b = fmaf(v.w, v.w, b);
    }
    float s = warp_sum(a + b);
    if (lane == 0) g_norm[gw] = s;
}

// direct squared distance between rows a,b (warp-cooperative, matches _pair_dist)
__device__ __forceinline__ float direct_d2(const float* __restrict__ batch,
                                           int a, int b, int lane)
{
    const float4* ra = (const float4*)(batch + (size_t)a * DIM);
    const float4* rb = (const float4*)(batch + (size_t)b * DIM);
    float c0 = 0.f, c1 = 0.f;
    #pragma unroll
    for (int q = 0; q < 4; q++) {
        float4 x = ra[lane + 32 * q];
        float4 y = rb[lane + 32 * q];
        float d;
        d = x.x - y.x; c0 = fmaf(d, d, c0);
        d = x.y - y.y; c1 = fmaf(d, d, c1);
        d = x.z - y.z; c0 = fmaf(d, d, c0);
        d = x.w - y.w; c1 = fmaf(d, d, c1);
    }
    return warp_sum(c0 + c1);
}

// ---------------------------------------------------------------------------
// Kernel 2: TWO warps per anchor (even/odd candidate slots), merged via smem.
// ---------------------------------------------------------------------------
__global__ void __launch_bounds__(128)
triplet_kernel(const float* __restrict__ batch,
               const int* __restrict__ anchors,
               const int* __restrict__ negatives,
               int n, float* __restrict__ out)
{
    __shared__ float s_best[2];
    __shared__ int   s_bj[2];
    __shared__ float s_sum;
    __shared__ int   s_cnt2;

    int w    = threadIdx.x >> 5;           // 0..3
    int lane = threadIdx.x & 31;
    int gw   = blockIdx.x * 4 + w;
    int slot = gw >> 1;                    // anchor slot in bucket order
    int half = gw & 1;

    if (threadIdx.x == 0) { s_sum = 0.f; s_cnt2 = 0; }

    float best  = INFINITY;
    int   bestj = INT_MAX;
    int   t = -1, s = 0, e = 0, cnt = 0;

    if (slot < n) {
        t   = g_bidx[slot];
        int lab = g_lab[t];
        s   = g_bstart[lab];
        e   = g_bstart[lab + 1];
        cnt = e - s;

        if (cnt > 2) {
            const float4* rt = (const float4*)(batch + (size_t)t * DIM);
            float4 xi0 = rt[lane];
            float4 xi1 = rt[lane + 32];
            float4 xi2 = rt[lane + 64];
            float4 xi3 = rt[lane + 96];

            // scan candidates p = s+half, s+half+2, ... ; 2 per iteration
            for (int p = s + half; p < e; p += 4) {
                int  p2 = p + 2;
                bool v1 = p2 < e;
                int j0 = g_bidx[p];
                int j1 = g_bidx[v1 ? p2 : p];
                float n0 = g_norm[j0];
                float n1 = g_norm[j1];
                const float4* r0 = (const float4*)(batch + (size_t)j0 * DIM);
                const float4* r1 = (const float4*)(batch + (size_t)j1 * DIM);

                float a0 = 0.f, b0 = 0.f, a1 = 0.f, b1 = 0.f;
                #pragma unroll
                for (int q = 0; q < 4; q++) {
                    float4 x  = (q == 0) ? xi0 : (q == 1) ? xi1 : (q == 2) ? xi2 : xi3;
                    float4 y0 = r0[lane + 32 * q];
                    float4 y1 = r1[lane + 32 * q];
                    a0 = fmaf(x.x, y0.x, a0); b0 = fmaf(x.y, y0.y, b0);
                    a0 = fmaf(x.z, y0.z, a0); b0 = fmaf(x.w, y0.w, b0);
                    a1 = fmaf(x.x, y1.x, a1); b1 = fmaf(x.y, y1.y, b1);
                    a1 = fmaf(x.z, y1.z, a1); b1 = fmaf(x.w, y1.w, b1);
                }
                float s0 = a0 + b0, s1 = a1 + b1;
                #pragma unroll
                for (int o = 16; o > 0; o >>= 1) {
                    s0 += __shfl_xor_sync(0xFFFFFFFFu, s0, o);
                    s1 += __shfl_xor_sync(0xFFFFFFFFu, s1, o);
                }
                float m0 = fmaf(-2.f, s0, n0);   // ||c||^2 - 2<a,c>
                float m1 = fmaf(-2.f, s1, n1);
                if (j0 != t && (m0 < best || (m0 == best && j0 < bestj)))
                    { best = m0; bestj = j0; }
                if (v1 && j1 != t && (m1 < best || (m1 == best && j1 < bestj)))
                    { best = m1; bestj = j1; }
            }
        }
    }

    // odd warp publishes its (best, bestj); even warp merges
    if (half == 1 && lane == 0) { s_best[w >> 1] = best; s_bj[w >> 1] = bestj; }
    __syncthreads();

    if (slot < n && cnt > 2 && half == 0) {
        float ob = s_best[w >> 1];
        int   oj = s_bj[w >> 1];
        if (ob < best || (ob == best && oj < bestj)) { best = ob; bestj = oj; }

        int a  = anchors[t];
        int ng = negatives[t];
        float dap2 = direct_d2(batch, a, bestj, lane);
        float dan2 = direct_d2(batch, a, ng,    lane);
        if (lane == 0) {
            float d_ap = sqrtf(fmaxf(dap2, 1e-12f));
            float d_an = sqrtf(fmaxf(dan2, 1e-12f));
            float z    = (d_ap - d_an) * 10.0f;   // (s_an - s_ap)/0.05
            float per  = fmaxf(z, 0.f) + log1pf(expf(-fabsf(z)));
            atomicAdd(&s_sum, per);
            atomicAdd(&s_cnt2, 1);
        }
    }

    __syncthreads();
    if (threadIdx.x == 0) {
        if (s_cnt2 > 0) {
            atomicAdd(&g_sum, s_sum);
            atomicAdd(&g_cnt, (float)s_cnt2);
        }
        __threadfence();
        int done = atomicAdd(&g_done, 1);
        if (done == (int)gridDim.x - 1) {
            float sum = atomicAdd(&g_sum, 0.0f);
            float cn  = atomicAdd(&g_cnt, 0.0f);
            out[0] = sum / cn;
        }
    }
}

// ---------------------------------------------------------------------------
extern "C" void kernel_launch(void* const* d_in, const int* in_sizes, int n_in,
                              void* d_out, int out_size)
{
    const float* batch     = (const float*)d_in[0];
    const int*   labels    = (const int*)d_in[1];
    const int*   anchors   = (const int*)d_in[2];
    const int*   negatives = (const int*)d_in[3];
    float*       out       = (float*)d_out;

    int n = in_sizes[1];
    int C = 128;

    build_kernel<<<1, 1024>>>(labels, n, C);
    norm_kernel<<<(n + 7) / 8, 256>>>(batch, n);

    int blocks = (2 * n + 3) / 4;          // 2 warps per anchor, 4 warps/block
    triplet_kernel<<<blocks, 128>>>(batch, anchors, negatives, n, out);
}